// round 6
// baseline (speedup 1.0000x reference)
#include <cuda_runtime.h>
#include <cuda_bf16.h>
#include <stdint.h>

#define M_PAIRS 4096
#define T_LEN   512
#define D_DIM   512
#define N_CAND  65
#define SPAN    4094u

// Device scratch (no allocations allowed). Zero-init at module load; counters
// self-reset each replay.
__device__ __nv_bfloat16 g_enc [M_PAIRS * D_DIM];
__device__ float         g_pred[M_PAIRS * D_DIM];
__device__ int           g_sel [M_PAIRS * N_CAND];
__device__ float         g_rowloss[M_PAIRS];
__device__ float         g_rowacc [M_PAIRS];
__device__ unsigned int  g_cnt1[64];
__device__ unsigned int  g_cnt2;

// ---------------- Threefry-2x32 (20 rounds), exact JAX semantics ------------
struct TFK { uint32_t a, b; };

__host__ __device__ constexpr TFK tf2x32_c(uint32_t k0, uint32_t k1,
                                           uint32_t x0, uint32_t x1) {
    uint32_t ks2 = 0x1BD11BDAu ^ k0 ^ k1;
    x0 += k0; x1 += k1;
#define TF_RND(R) { x0 += x1; x1 = (x1 << (R)) | (x1 >> (32 - (R))); x1 ^= x0; }
    TF_RND(13) TF_RND(15) TF_RND(26) TF_RND(6)
    x0 += k1;  x1 += ks2 + 1u;
    TF_RND(17) TF_RND(29) TF_RND(16) TF_RND(24)
    x0 += ks2; x1 += k0 + 2u;
    TF_RND(13) TF_RND(15) TF_RND(26) TF_RND(6)
    x0 += k0;  x1 += k1 + 3u;
    TF_RND(17) TF_RND(29) TF_RND(16) TF_RND(24)
    x0 += k1;  x1 += ks2 + 4u;
    TF_RND(13) TF_RND(15) TF_RND(26) TF_RND(6)
    x0 += ks2; x1 += k0 + 5u;
#undef TF_RND
    return TFK{x0, x1};
}

__device__ constexpr TFK SK1 = tf2x32_c(0u, 42u, 0u, 0u);  // split(key(42))[0]
__device__ constexpr TFK SK2 = tf2x32_c(0u, 42u, 0u, 1u);  // split(key(42))[1]

// ---------------- packed f32x2 helpers ---------------------------------------
// bf16 pair (packed u32) -> f32x2 via shift/mask (exact), fused multiply-add.
__device__ __forceinline__ void bfma2(unsigned long long& acc, uint32_t u,
                                      unsigned long long p2) {
    asm("{\n\t"
        ".reg .b32 lo, hi;\n\t"
        ".reg .b64 e;\n\t"
        "shl.b32 lo, %1, 16;\n\t"
        "and.b32 hi, %1, 0xFFFF0000;\n\t"
        "mov.b64 e, {lo, hi};\n\t"
        "fma.rn.f32x2 %0, e, %2, %0;\n\t"
        "}" : "+l"(acc) : "r"(u), "l"(p2));
}
__device__ __forceinline__ unsigned long long packf2(float lo, float hi) {
    unsigned long long r;
    asm("mov.b64 %0, {%1, %2};" : "=l"(r) : "f"(lo), "f"(hi));
    return r;
}
__device__ __forceinline__ float hadd2(unsigned long long a) {
    float lo, hi;
    asm("mov.b64 {%0, %1}, %2;" : "=f"(lo), "=f"(hi) : "l"(a));
    return lo + hi;
}

// ---------------- Kernel 1: gather + L2 norm + threefry sel table -----------
__global__ void __launch_bounds__(256)
gather_norm_kernel(const float* __restrict__ pred,
                   const float* __restrict__ enc,
                   const void*  __restrict__ mask) {
    int m    = blockIdx.x;
    int tid  = threadIdx.x;
    int half = tid >> 7;        // 0: encoded, 1: predicted
    int ht   = tid & 127;
    int warp = tid >> 5, lane = tid & 31;

    __shared__ int   s_is64;
    __shared__ float red[8];

    // dtype probe: fixed 512B window; int32 mask odd words = cols (not all 0),
    // int64 mask odd words = hi-words (all 0).
    if (warp == 0) {
        int4 w = ((const int4*)mask)[lane];
        unsigned any = __ballot_sync(0xFFFFFFFFu, (w.y | w.w) != 0);
        if (lane == 0) s_is64 = (any == 0u) ? 1 : 0;
    }
    __syncthreads();
    int is64 = s_is64;

    // negative-selection table (hidden under the DRAM-bound gather)
    if (tid < 64) {
        uint32_t t = (uint32_t)m * 64u + (uint32_t)tid;
        TFK A = tf2x32_c(SK1.a, SK1.b, 0u, t);
        TFK B = tf2x32_c(SK2.a, SK2.b, 0u, t);
        uint32_t r;
        if (!is64) {
            uint32_t hi = A.a ^ A.b, lo = B.a ^ B.b;
            r = ((hi % SPAN) * 1024u + (lo % SPAN)) % SPAN;
        } else {
            unsigned long long hi = (((unsigned long long)A.a) << 32) | A.b;
            unsigned long long lo = (((unsigned long long)B.a) << 32) | B.b;
            r = (uint32_t)(((hi % 4094ull) * 512ull + (lo % 4094ull)) % 4094ull);
        }
        g_sel[m * N_CAND + tid + 1] = (int)r + (((int)r >= m) ? 1 : 0);
    }
    if (tid == 64) g_sel[m * N_CAND] = m;

    long long row, col;
    if (is64) {
        const long long* mm = (const long long*)mask;
        row = mm[2 * m]; col = mm[2 * m + 1];
    } else {
        const int* mm = (const int*)mask;
        row = mm[2 * m]; col = mm[2 * m + 1];
    }
    long long base = (row * (long long)T_LEN + col) * (long long)D_DIM;

    const float* src = half ? pred : enc;
    float4 v = ((const float4*)(src + base))[ht];
    float ssq = v.x*v.x + v.y*v.y + v.z*v.z + v.w*v.w;
    #pragma unroll
    for (int o = 16; o; o >>= 1) ssq += __shfl_xor_sync(0xFFFFFFFFu, ssq, o);
    if (lane == 0) red[warp] = ssq;
    __syncthreads();
    float tot = red[half * 4 + 0] + red[half * 4 + 1]
              + red[half * 4 + 2] + red[half * 4 + 3];
    float inv = 1.0f / fmaxf(sqrtf(tot), 1e-12f);
    if (half == 0) {
        __nv_bfloat162 b0 = __floats2bfloat162_rn(v.x * inv, v.y * inv);
        __nv_bfloat162 b1 = __floats2bfloat162_rn(v.z * inv, v.w * inv);
        uint32_t u0 = *reinterpret_cast<uint32_t*>(&b0);
        uint32_t u1 = *reinterpret_cast<uint32_t*>(&b1);
        ((uint2*)(g_enc + (size_t)m * D_DIM))[ht] = make_uint2(u0, u1);
    } else {
        ((float4*)(g_pred + (size_t)m * D_DIM))[ht] =
            make_float4(v.x*inv, v.y*inv, v.z*inv, v.w*inv);
    }
}

// ---------------- candidate dot: 16 elems/lane, FFMA2 + shift-convert -------
__device__ __forceinline__ float cand_dot2(const uint4* __restrict__ e8,
                                           int lane,
                                           const unsigned long long p2[8]) {
    unsigned long long acc = 0ull;   // f32x2 {0,0}
    uint4 v0 = e8[lane];
    uint4 v1 = e8[32 + lane];
    bfma2(acc, v0.x, p2[0]);
    bfma2(acc, v0.y, p2[1]);
    bfma2(acc, v0.z, p2[2]);
    bfma2(acc, v0.w, p2[3]);
    bfma2(acc, v1.x, p2[4]);
    bfma2(acc, v1.y, p2[5]);
    bfma2(acc, v1.z, p2[6]);
    bfma2(acc, v1.w, p2[7]);
    return hadd2(acc);
}

// ---------------- Kernel 2: sims + LSE + argmax + tree-fused reduce ---------
__global__ void __launch_bounds__(256)
sim_kernel(float* __restrict__ out, int out_size) {
    int m    = blockIdx.x;
    int tid  = threadIdx.x;
    int warp = tid >> 5, lane = tid & 31;

    __shared__ int   sel[N_CAND];
    __shared__ float sims[N_CAND];

    if (tid < N_CAND) sel[tid] = g_sel[m * N_CAND + tid];

    // stage this lane's 16 pred elements as 8 packed f32x2
    unsigned long long p2[8];
    {
        const float4* p4 = (const float4*)(g_pred + (size_t)m * D_DIM);
        #pragma unroll
        for (int j = 0; j < 2; j++) {
            float4 a = p4[j * 64 + lane * 2];
            float4 b = p4[j * 64 + lane * 2 + 1];
            p2[j*4 + 0] = packf2(a.x, a.y);
            p2[j*4 + 1] = packf2(a.z, a.w);
            p2[j*4 + 2] = packf2(b.x, b.y);
            p2[j*4 + 3] = packf2(b.z, b.w);
        }
    }
    __syncthreads();

    // 65 dots, 8 warps, 2 candidates in flight per warp
    {
        int c = warp;
        while (c + 8 < N_CAND) {
            const uint4* eA = (const uint4*)(g_enc + (size_t)sel[c]     * D_DIM);
            const uint4* eB = (const uint4*)(g_enc + (size_t)sel[c + 8] * D_DIM);
            float a0 = cand_dot2(eA, lane, p2);
            float a1 = cand_dot2(eB, lane, p2);
            #pragma unroll
            for (int o = 16; o; o >>= 1) {
                a0 += __shfl_xor_sync(0xFFFFFFFFu, a0, o);
                a1 += __shfl_xor_sync(0xFFFFFFFFu, a1, o);
            }
            if (lane == 0) { sims[c] = a0 * 10.0f; sims[c + 8] = a1 * 10.0f; }
            c += 16;
        }
        if (c < N_CAND) {
            const uint4* eA = (const uint4*)(g_enc + (size_t)sel[c] * D_DIM);
            float a0 = cand_dot2(eA, lane, p2);
            #pragma unroll
            for (int o = 16; o; o >>= 1) a0 += __shfl_xor_sync(0xFFFFFFFFu, a0, o);
            if (lane == 0) sims[c] = a0 * 10.0f;
        }
    }
    __syncthreads();

    // warp-parallel LSE / argmax (warp 0)
    if (warp == 0) {
        float v0 = sims[lane];
        float v1 = sims[lane + 32];
        float v2 = (lane == 0) ? sims[64] : -3.4e38f;
        float mx = fmaxf(fmaxf(v0, v1), v2);
        #pragma unroll
        for (int o = 16; o; o >>= 1) mx = fmaxf(mx, __shfl_xor_sync(0xFFFFFFFFu, mx, o));
        float s = expf(v0 - mx) + expf(v1 - mx) + ((lane == 0) ? expf(v2 - mx) : 0.0f);
        #pragma unroll
        for (int o = 16; o; o >>= 1) s += __shfl_xor_sync(0xFFFFFFFFu, s, o);
        if (lane == 0) {
            float s0 = sims[0];
            g_rowloss[m] = mx + logf(s) - s0;
            g_rowacc[m]  = (s0 >= mx) ? 1.0f : 0.0f;
        }
    }

    // two-level arrival tree + fused deterministic final reduce
    __shared__ bool last;
    __syncthreads();
    __threadfence();
    if (tid == 0) {
        bool l = false;
        if (atomicAdd(&g_cnt1[m >> 6], 1u) == 63u) {
            if (atomicAdd(&g_cnt2, 1u) == 63u) l = true;
        }
        last = l;
    }
    __syncthreads();
    if (!last) return;
    __threadfence();

    if (tid < 64) g_cnt1[tid] = 0u;     // self-reset for next replay
    if (tid == 64) g_cnt2 = 0u;

    float sl = 0.0f, sa = 0.0f;
    #pragma unroll
    for (int k = 0; k < M_PAIRS / 256; k++) {
        int i = k * 256 + tid;
        sl += g_rowloss[i];
        sa += g_rowacc[i];
    }
    __shared__ float bl[8], ba[8];
    #pragma unroll
    for (int o = 16; o; o >>= 1) {
        sl += __shfl_xor_sync(0xFFFFFFFFu, sl, o);
        sa += __shfl_xor_sync(0xFFFFFFFFu, sa, o);
    }
    if (lane == 0) { bl[warp] = sl; ba[warp] = sa; }
    __syncthreads();
    if (tid == 0) {
        float tl = 0.0f, ta = 0.0f;
        #pragma unroll
        for (int w = 0; w < 8; w++) { tl += bl[w]; ta += ba[w]; }
        out[0] = tl / (float)M_PAIRS;
        if (out_size > 1) out[1] = ta / (float)M_PAIRS;
    }
}

// ---------------- Launch ----------------------------------------------------
extern "C" void kernel_launch(void* const* d_in, const int* in_sizes, int n_in,
                              void* d_out, int out_size) {
    const float* pred = (const float*)d_in[0];
    const float* enc  = (const float*)d_in[1];
    const void*  mask = d_in[2];

    gather_norm_kernel<<<M_PAIRS, 256>>>(pred, enc, mask);
    sim_kernel<<<M_PAIRS, 256>>>((float*)d_out, out_size);
}